// round 10
// baseline (speedup 1.0000x reference)
#include <cuda_runtime.h>
#include <cuda_bf16.h>
#include <cstdint>

#define DIM     1024
#define BATCH   16384
#define NLAYERS 18

// ---------------- main GEMM tiling ----------------
#define BM 128
#define BN 128
#define BK 32                     // = 2 quant groups of 16
#define NCHUNK (DIM / BK)         // 32

// stage: XH 8K | XL 8K | WQ 8K | SC 1K, padded to 32KB; 2 stages = 64KB/CTA
#define OFF_XL 8192u
#define OFF_WQ 16384u
#define OFF_SC 24576u
#define STAGE  32768u
#define SM_TOTAL (2 * 32768)
// lora epilogue staging (in stage 0): UH 0 | UL 8192 | BH 16384 | BL 24576

// k_lora smem: XH 4K | XL 4K | AH 2K | AL 2K -> 12KB/stage, 2 stages
#define L_AH 8192u
#define L_AL 10240u
#define L_STAGE 12288u
#define L_SMEM (2 * 12288)

// ---------------- static device scratch ----------------
__device__ __align__(16) __nv_bfloat16 g_Wq [NLAYERS * DIM * DIM];       // exact 2q-15
__device__ __align__(16) float         g_Sc [NLAYERS * 64 * DIM];        // [l][g][o] = s[l][o][g]/15
__device__ __align__(16) __nv_bfloat16 g_lAh[NLAYERS * 32 * DIM];
__device__ __align__(16) __nv_bfloat16 g_lAl[NLAYERS * 32 * DIM];
__device__ __align__(16) __nv_bfloat16 g_Bh [NLAYERS * DIM * 32];
__device__ __align__(16) __nv_bfloat16 g_Bl [NLAYERS * DIM * 32];
__device__ __align__(16) __nv_bfloat16 g_Uh [BATCH * 32];
__device__ __align__(16) __nv_bfloat16 g_Ul [BATCH * 32];
__device__ __align__(16) __nv_bfloat16 g_A0h[BATCH * DIM];
__device__ __align__(16) __nv_bfloat16 g_A0l[BATCH * DIM];
__device__ __align__(16) __nv_bfloat16 g_A1h[BATCH * DIM];
__device__ __align__(16) __nv_bfloat16 g_A1l[BATCH * DIM];
__device__ __align__(16) __nv_bfloat16 g_Rh [BATCH * DIM];
__device__ __align__(16) __nv_bfloat16 g_Rl [BATCH * DIM];

// ---------------- PTX helpers ----------------
__device__ __forceinline__ uint32_t smem_u32(const void* p) {
    uint32_t a;
    asm("{ .reg .u64 t; cvta.to.shared.u64 t, %1; cvt.u32.u64 %0, t; }" : "=r"(a) : "l"(p));
    return a;
}
#define CP_ASYNC16(dst, src) \
    asm volatile("cp.async.cg.shared.global [%0], [%1], 16;\n" :: "r"(dst), "l"(src))
#define CP_COMMIT() asm volatile("cp.async.commit_group;\n" ::: "memory")
#define CP_WAIT0()  asm volatile("cp.async.wait_group 0;\n" ::: "memory")

#define LDSM_X4(r0, r1, r2, r3, addr) \
    asm volatile("ldmatrix.sync.aligned.m8n8.x4.shared.b16 {%0,%1,%2,%3}, [%4];\n" \
                 : "=r"(r0), "=r"(r1), "=r"(r2), "=r"(r3) : "r"(addr))
#define LDS_B64(u, addr) \
    asm volatile("ld.shared.b64 %0, [%1];\n" : "=l"(u) : "r"(addr))

#define MMA4(d, a0, a1, a2, a3, b0, b1) \
    asm volatile("mma.sync.aligned.m16n8k16.row.col.f32.bf16.bf16.f32 " \
                 "{%0,%1,%2,%3},{%4,%5,%6,%7},{%8,%9},{%0,%1,%2,%3};\n" \
                 : "+f"((d)[0]), "+f"((d)[1]), "+f"((d)[2]), "+f"((d)[3]) \
                 : "r"(a0), "r"(a1), "r"(a2), "r"(a3), "r"(b0), "r"(b1))
#define MMA4Z(d, a0, a1, a2, a3, b0, b1) \
    asm volatile("mma.sync.aligned.m16n8k16.row.col.f32.bf16.bf16.f32 " \
                 "{%0,%1,%2,%3},{%4,%5,%6,%7},{%8,%9},{%10,%10,%10,%10};\n" \
                 : "=f"((d)[0]), "=f"((d)[1]), "=f"((d)[2]), "=f"((d)[3]) \
                 : "r"(a0), "r"(a1), "r"(a2), "r"(a3), "r"(b0), "r"(b1), "f"(0.0f))

// packed f32x2 helpers (base sm_100 PTX feature, valid on compute_103)
#define PACK2(u, lo, hi) \
    asm volatile("mov.b64 %0, {%1, %2};\n" : "=l"(u) : "f"(lo), "f"(hi))
#define UNPACK2(lo, hi, u) \
    asm volatile("mov.b64 {%0, %1}, %2;\n" : "=f"(lo), "=f"(hi) : "l"(u))
#define FMA2(a, b, c) \
    asm volatile("fma.rn.f32x2 %0, %1, %2, %0;\n" : "+l"(a) : "l"(b), "l"(c))

__device__ __forceinline__ void split1(float v, __nv_bfloat16& h, __nv_bfloat16& l) {
    h = __float2bfloat16(v);
    l = __float2bfloat16(v - __bfloat162float(h));
}

// swizzle for 64B rows (verified R6): 16B-group g XOR (row & 3)
__device__ __forceinline__ uint32_t swz64(uint32_t row, uint32_t g16) {
    return row * 64u + ((g16 ^ (row & 3u)) << 4);
}

// ---------------- main GEMM chunk loader ----------------
__device__ __forceinline__ void load_main(
    uint32_t st, uint32_t d0a, uint32_t d0b,
    const char* pXh, const char* pXl, const char* pWq, size_t off,
    const char* pScChunk, int tid)
{
    CP_ASYNC16(st + d0a,          pXh + off);
    CP_ASYNC16(st + d0b,          pXh + off + 16);
    CP_ASYNC16(st + OFF_XL + d0a, pXl + off);
    CP_ASYNC16(st + OFF_XL + d0b, pXl + off + 16);
    CP_ASYNC16(st + OFF_WQ + d0a, pWq + off);
    CP_ASYNC16(st + OFF_WQ + d0b, pWq + off + 16);
    if (tid < 64) {
        uint32_t gg = (uint32_t)(tid >> 5);
        uint32_t oo = (uint32_t)((tid & 31) * 16);
        CP_ASYNC16(st + OFF_SC + gg * 512u + oo, pScChunk + (size_t)gg * 4096 + oo);
    }
    CP_COMMIT();
}

__device__ __forceinline__ void load_lora_stage(
    uint32_t sb, uint32_t d0a, uint32_t d0b,
    const char* pUh, const char* pUl, const char* pBh, const char* pBl, size_t off)
{
    CP_ASYNC16(sb + d0a,          pUh + off);
    CP_ASYNC16(sb + d0b,          pUh + off + 16);
    CP_ASYNC16(sb + 8192u + d0a,  pUl + off);
    CP_ASYNC16(sb + 8192u + d0b,  pUl + off + 16);
    CP_ASYNC16(sb + 16384u + d0a, pBh + off);
    CP_ASYNC16(sb + 16384u + d0b, pBh + off + 16);
    CP_ASYNC16(sb + 24576u + d0a, pBl + off);
    CP_ASYNC16(sb + 24576u + d0b, pBl + off + 16);
    CP_COMMIT();
}

// ---------------- fused block-scaled GEMM layer ----------------
// C = x @ W^T, W = Wint * s[o,g] exact; per group d = (xh+xl)@Wint, acc += s*d.
// Inner loop is latency-scheduled: 4 independent Z-MMAs, 4 dependent adds,
// then batched PACK/FMA2 (reads target dz values issued >=8 slots earlier).
template<int MODE>
__global__ void __launch_bounds__(256, 2)
k_gemm(const __nv_bfloat16* __restrict__ Xh, const __nv_bfloat16* __restrict__ Xl,
       const __nv_bfloat16* __restrict__ Wq, const float* __restrict__ Sc,
       const float* __restrict__ bias,
       const __nv_bfloat16* __restrict__ Uh, const __nv_bfloat16* __restrict__ Ul,
       const __nv_bfloat16* __restrict__ Bh, const __nv_bfloat16* __restrict__ Bl,
       __nv_bfloat16* __restrict__ Oh, __nv_bfloat16* __restrict__ Ol,
       const __nv_bfloat16* __restrict__ Rh, const __nv_bfloat16* __restrict__ Rl,
       float* __restrict__ Of)
{
    extern __shared__ char smem[];
    const uint32_t sb = smem_u32(smem);
    const int tid = threadIdx.x, wid = tid >> 5, lane = tid & 31;
    const int Mb = blockIdx.y * BM, Nb = blockIdx.x * BN;
    const int wm = (wid & 1) * 64;
    const int wn = (wid >> 1) * 32;

    const char* pXh = (const char*)(Xh + (size_t)Mb * DIM);
    const char* pXl = (const char*)(Xl + (size_t)Mb * DIM);
    const char* pWq = (const char*)(Wq + (size_t)Nb * DIM);
    const char* pSc = (const char*)(Sc + Nb);

    const uint32_t d0a = swz64((uint32_t)(tid >> 1), (uint32_t)((tid & 1) * 2));
    const uint32_t d0b = swz64((uint32_t)(tid >> 1), (uint32_t)((tid & 1) * 2 + 1));
    const size_t goff0 = (size_t)(tid >> 1) * 2048 + (size_t)((tid & 1) * 32);

    const int l7  = lane & 7;
    const int l15 = lane & 15;
    const int lhi = lane >> 4;
    const int lb8 = ((lane >> 3) & 1) << 3;
    const int tg  = lane & 3;

    uint32_t adA[2][4], adB[2][2];
#pragma unroll
    for (int kk = 0; kk < 2; kk++) {
#pragma unroll
        for (int mi = 0; mi < 4; mi++)
            adA[kk][mi] = swz64((uint32_t)(wm + mi * 16 + l15), (uint32_t)(2 * kk + lhi));
#pragma unroll
        for (int j = 0; j < 2; j++)
            adB[kk][j] = swz64((uint32_t)(wn + j * 16 + l7 + lb8), (uint32_t)(2 * kk + lhi));
    }

    unsigned long long acc64[4][4][2];
#pragma unroll
    for (int mi = 0; mi < 4; mi++)
#pragma unroll
        for (int ni = 0; ni < 4; ni++) { acc64[mi][ni][0] = 0ull; acc64[mi][ni][1] = 0ull; }

    load_main(sb, d0a, d0b, pXh, pXl, pWq, goff0, pSc, tid);

#pragma unroll 1
    for (int c = 0; c < NCHUNK; c++) {
        CP_WAIT0();
        __syncthreads();
        if (c + 1 < NCHUNK) {
            load_main(sb + (uint32_t)((c + 1) & 1) * STAGE, d0a, d0b,
                      pXh, pXl, pWq, goff0 + (size_t)(c + 1) * 64,
                      pSc + (size_t)(c + 1) * 8192, tid);
        } else {
            load_lora_stage(sb, d0a, d0b,
                            (const char*)(Uh + (size_t)Mb * 32),
                            (const char*)(Ul + (size_t)Mb * 32),
                            (const char*)(Bh + (size_t)Nb * 32),
                            (const char*)(Bl + (size_t)Nb * 32),
                            (size_t)(tid >> 1) * 64 + (size_t)((tid & 1) * 32));
        }

        const uint32_t st = sb + (uint32_t)(c & 1) * STAGE;
        const uint32_t stXh = st, stXl = st + OFF_XL, stWq = st + OFF_WQ, stSc = st + OFF_SC;
#pragma unroll
        for (int kk = 0; kk < 2; kk++) {
            unsigned long long s01[4];
#pragma unroll
            for (int ni = 0; ni < 4; ni++)
                LDS_B64(s01[ni], stSc + (uint32_t)kk * 512u
                                      + (uint32_t)((wn + ni * 8 + tg * 2) * 4));
            uint32_t bW[8];
            LDSM_X4(bW[0], bW[1], bW[2], bW[3], stWq + adB[kk][0]);
            LDSM_X4(bW[4], bW[5], bW[6], bW[7], stWq + adB[kk][1]);
#pragma unroll
            for (int mi = 0; mi < 4; mi++) {
                uint32_t xh4[4], xl4[4];
                LDSM_X4(xh4[0], xh4[1], xh4[2], xh4[3], stXh + adA[kk][mi]);
                LDSM_X4(xl4[0], xl4[1], xl4[2], xl4[3], stXl + adA[kk][mi]);
                float dz[4][4];
                // 4 independent zero-init MMAs
                MMA4Z(dz[0], xh4[0], xh4[1], xh4[2], xh4[3], bW[0], bW[2]);
                MMA4Z(dz[1], xh4[0], xh4[1], xh4[2], xh4[3], bW[1], bW[3]);
                MMA4Z(dz[2], xh4[0], xh4[1], xh4[2], xh4[3], bW[4], bW[6]);
                MMA4Z(dz[3], xh4[0], xh4[1], xh4[2], xh4[3], bW[5], bW[7]);
                // 4 dependent adds (each target issued 4 MMA slots earlier)
                MMA4(dz[0], xl4[0], xl4[1], xl4[2], xl4[3], bW[0], bW[2]);
                MMA4(dz[1], xl4[0], xl4[1], xl4[2], xl4[3], bW[1], bW[3]);
                MMA4(dz[2], xl4[0], xl4[1], xl4[2], xl4[3], bW[4], bW[6]);
                MMA4(dz[3], xl4[0], xl4[1], xl4[2], xl4[3], bW[5], bW[7]);
                // batched scale-apply (dz[0] is 8 MMA issues old here)
#pragma unroll
                for (int ni = 0; ni < 4; ni++) {
                    unsigned long long d01, d23;
                    PACK2(d01, dz[ni][0], dz[ni][1]);
                    PACK2(d23, dz[ni][2], dz[ni][3]);
                    FMA2(acc64[mi][ni][0], d01, s01[ni]);
                    FMA2(acc64[mi][ni][1], d23, s01[ni]);
                }
            }
        }
    }

    // unpack accumulators for the LoRA chunk + epilogue
    float acc[4][4][4];
#pragma unroll
    for (int mi = 0; mi < 4; mi++)
#pragma unroll
        for (int ni = 0; ni < 4; ni++) {
            UNPACK2(acc[mi][ni][0], acc[mi][ni][1], acc64[mi][ni][0]);
            UNPACK2(acc[mi][ni][2], acc[mi][ni][3], acc64[mi][ni][1]);
        }

    // ---- LoRA chunk: acc += U @ B^T (k=32, 3-term bf16-pair) ----
    CP_WAIT0();
    __syncthreads();
    {
        const uint32_t sU = sb, sUl = sb + 8192u, sB = sb + 16384u, sBl = sb + 24576u;
#pragma unroll
        for (int kk = 0; kk < 2; kk++) {
            uint32_t bB[8], bL[8];
            LDSM_X4(bB[0], bB[1], bB[2], bB[3], sB + adB[kk][0]);
            LDSM_X4(bB[4], bB[5], bB[6], bB[7], sB + adB[kk][1]);
            LDSM_X4(bL[0], bL[1], bL[2], bL[3], sBl + adB[kk][0]);
            LDSM_X4(bL[4], bL[5], bL[6], bL[7], sBl + adB[kk][1]);
#pragma unroll
            for (int mi = 0; mi < 4; mi++) {
                uint32_t uh4[4], ul4[4];
                LDSM_X4(uh4[0], uh4[1], uh4[2], uh4[3], sU + adA[kk][mi]);
                LDSM_X4(ul4[0], ul4[1], ul4[2], ul4[3], sUl + adA[kk][mi]);
#pragma unroll
                for (int ni = 0; ni < 4; ni++) {
                    const int jb = (ni >> 1) * 4 + (ni & 1);
                    MMA4(acc[mi][ni], uh4[0], uh4[1], uh4[2], uh4[3], bB[jb], bB[jb + 2]);
                    MMA4(acc[mi][ni], ul4[0], ul4[1], ul4[2], ul4[3], bB[jb], bB[jb + 2]);
                    MMA4(acc[mi][ni], uh4[0], uh4[1], uh4[2], uh4[3], bL[jb], bL[jb + 2]);
                }
            }
        }
    }

    // ---- epilogue ----
    auto emit = [&](int r, int c, float v0, float v1) {
        size_t off = (size_t)r * DIM + c;
        if (MODE >= 1) {
            __nv_bfloat162 rh2 = *reinterpret_cast<const __nv_bfloat162*>(Rh + off);
            __nv_bfloat162 rl2 = *reinterpret_cast<const __nv_bfloat162*>(Rl + off);
            v0 += __bfloat162float(rh2.x) + __bfloat162float(rl2.x);
            v1 += __bfloat162float(rh2.y) + __bfloat162float(rl2.y);
        }
        if (MODE == 0) { v0 = fmaxf(v0, 0.f); v1 = fmaxf(v1, 0.f); }
        if (MODE == 2) {
            *reinterpret_cast<float2*>(Of + off) = make_float2(v0, v1);
        } else {
            __nv_bfloat16 h0, l0, h1, l1;
            split1(v0, h0, l0); split1(v1, h1, l1);
            __nv_bfloat162 H; H.x = h0; H.y = h1;
            __nv_bfloat162 L; L.x = l0; L.y = l1;
            *reinterpret_cast<__nv_bfloat162*>(Oh + off) = H;
            *reinterpret_cast<__nv_bfloat162*>(Ol + off) = L;
        }
    };

    const int gr = lane >> 2;
#pragma unroll
    for (int mi = 0; mi < 4; mi++) {
#pragma unroll
        for (int ni = 0; ni < 4; ni++) {
            int r0 = Mb + wm + mi * 16 + gr;
            int c0 = Nb + wn + ni * 8 + tg * 2;
            float b0 = __ldg(bias + c0), b1 = __ldg(bias + c0 + 1);
            emit(r0,     c0, acc[mi][ni][0] + b0, acc[mi][ni][1] + b1);
            emit(r0 + 8, c0, acc[mi][ni][2] + b0, acc[mi][ni][3] + b1);
        }
    }
}

// ---------------- LoRA U = x @ A^T (64-row blocks, 128 threads, 256 CTAs) ----------------
__global__ void __launch_bounds__(128, 4)
k_lora(const __nv_bfloat16* __restrict__ Xh, const __nv_bfloat16* __restrict__ Xl,
       const __nv_bfloat16* __restrict__ Ath, const __nv_bfloat16* __restrict__ Atl,
       __nv_bfloat16* __restrict__ Uh, __nv_bfloat16* __restrict__ Ul)
{
    extern __shared__ char smem[];
    const uint32_t sb = smem_u32(smem);
    const int tid = threadIdx.x, wid = tid >> 5, lane = tid & 31;
    const int Mb = blockIdx.x * 64;
    const int wm = wid * 16;

    const char* pXh = (const char*)(Xh + (size_t)Mb * DIM);
    const char* pXl = (const char*)(Xl + (size_t)Mb * DIM);
    const char* pAh = (const char*)Ath;
    const char* pAl = (const char*)Atl;

    // X loader: row = tid>>1 (0..63), groups (tid&1)*2, +1
    const uint32_t d0a = swz64((uint32_t)(tid >> 1), (uint32_t)((tid & 1) * 2));
    const uint32_t d0b = swz64((uint32_t)(tid >> 1), (uint32_t)((tid & 1) * 2 + 1));
    const size_t goff0 = (size_t)(tid >> 1) * 2048 + (size_t)((tid & 1) * 32);
    // A loader: 2 slots per thread (slot = tid and tid+128; 256 slots total)
    uint32_t aDst[2]; size_t aSrc[2]; const char* pA[2];
#pragma unroll
    for (int s = 0; s < 2; s++) {
        int slot = tid + s * 128;
        int arr = slot >> 7;             // 0: Ah, 1: Al
        int row = (slot >> 2) & 31;
        int g   = slot & 3;
        aDst[s] = (arr ? L_AL : L_AH) + swz64((uint32_t)row, (uint32_t)g);
        aSrc[s] = (size_t)row * 2048 + (size_t)g * 16;
        pA[s]   = arr ? pAl : pAh;
    }

    const int l7 = lane & 7, l15 = lane & 15, lhi = lane >> 4;
    const int lb8 = ((lane >> 3) & 1) << 3, tg = lane & 3;

    uint32_t adA[2], adB[2][2];
#pragma unroll
    for (int kk = 0; kk < 2; kk++) {
        adA[kk] = swz64((uint32_t)(wm + l15), (uint32_t)(2 * kk + lhi));
#pragma unroll
        for (int j = 0; j < 2; j++)
            adB[kk][j] = swz64((uint32_t)(j * 16 + l7 + lb8), (uint32_t)(2 * kk + lhi));
    }

    float acc[4][4];
#pragma unroll
    for (int ni = 0; ni < 4; ni++)
#pragma unroll
        for (int k = 0; k < 4; k++) acc[ni][k] = 0.f;

    {
        CP_ASYNC16(sb + d0a, pXh + goff0); CP_ASYNC16(sb + d0b, pXh + goff0 + 16);
        CP_ASYNC16(sb + 4096u + d0a, pXl + goff0); CP_ASYNC16(sb + 4096u + d0b, pXl + goff0 + 16);
        CP_ASYNC16(sb + aDst[0], pA[0] + aSrc[0]);
        CP_ASYNC16(sb + aDst[1], pA[1] + aSrc[1]);
        CP_COMMIT();
    }

#pragma unroll 1
    for (int c = 0; c < NCHUNK; c++) {
        CP_WAIT0();
        __syncthreads();
        if (c + 1 < NCHUNK) {
            const uint32_t st2 = sb + (uint32_t)((c + 1) & 1) * L_STAGE;
            const size_t o2 = goff0 + (size_t)(c + 1) * 64;
            const size_t ka = (size_t)(c + 1) * 64;
            CP_ASYNC16(st2 + d0a, pXh + o2); CP_ASYNC16(st2 + d0b, pXh + o2 + 16);
            CP_ASYNC16(st2 + 4096u + d0a, pXl + o2); CP_ASYNC16(st2 + 4096u + d0b, pXl + o2 + 16);
            CP_ASYNC16(st2 + aDst[0], pA[0] + aSrc[0] + ka);
            CP_ASYNC16(st2 + aDst[1], pA[1] + aSrc[1] + ka);
            CP_COMMIT();
        }
        const uint32_t st = sb + (uint32_t)(c & 1) * L_STAGE;
#pragma unroll
        for (int kk = 0; kk < 2; kk++) {
            uint32_t bA[8], bAl[8];
            LDSM_X4(bA[0], bA[1], bA[2], bA[3], st + L_AH + adB[kk][0]);
            LDSM_X4(bA[4], bA[5], bA[6], bA[7], st + L_AH + adB[kk][1]);
            LDSM_X4(bAl[0], bAl[1], bAl[2], bAl[3], st + L_AL + adB[kk][0]);
            LDSM_X4(bAl[4], bAl[5], bAl[6], bAl[7], st + L_AL + adB[kk][1]);
            uint32_t xh4[4], xl4[4];
            LDSM_X4(xh4[0], xh4[1], xh4[2], xh4[3], st + adA[kk]);
            LDSM_X4(xl4[0], xl4[1], xl4[2], xl4[3], st + 4096u + adA[kk]);
#pragma unroll
            for (int ni = 0; ni < 4; ni++) {
                const int jb = (ni >> 1) * 4 + (ni & 1);
                MMA4(acc[ni], xh4[0], xh4[1], xh4[2], xh4[3], bA[jb],  bA[jb + 2]);
                MMA4(acc[ni], xl4[0], xl4[1], xl4[2], xl4[3], bA[jb],  bA[jb + 2]);
                MMA4(acc[ni], xh4[0], xh4[1], xh4[2], xh4[3], bAl[jb], bAl[jb + 2]);
            }
        }
    }

    const int gr = lane >> 2;
#pragma unroll
    for (int ni = 0; ni < 4; ni++) {
        int r0 = Mb + wm + gr;
        int c0 = ni * 8 + tg * 2;
        __nv_bfloat16 h0, l0, h1, l1;
        split1(acc[ni][0], h0, l0); split1(acc[ni][1], h1, l1);
        __nv_bfloat162 H; H.x = h0; H.y = h1;
        __nv_bfloat162 L; L.x = l0; L.y = l1;
        *reinterpret_cast<__nv_bfloat162*>(Uh + (size_t)r0 * 32 + c0) = H;
        *reinterpret_cast<__nv_bfloat162*>(Ul + (size_t)r0 * 32 + c0) = L;
        split1(acc[ni][2], h0, l0); split1(acc[ni][3], h1, l1);
        H.x = h0; H.y = h1; L.x = l0; L.y = l1;
        *reinterpret_cast<__nv_bfloat162*>(Uh + (size_t)(r0 + 8) * 32 + c0) = H;
        *reinterpret_cast<__nv_bfloat162*>(Ul + (size_t)(r0 + 8) * 32 + c0) = L;
    }
}

// ---------------- prep kernels ----------------
__global__ void k_prepW(const int* __restrict__ qw) {
    int idx = blockIdx.x * 256 + threadIdx.x;
    g_Wq[idx] = __float2bfloat16((float)(2 * qw[idx] - 15));
}
__global__ void k_prepS(const float* __restrict__ scale) {
    int idx = blockIdx.x * 256 + threadIdx.x;
    int l = idx >> 16, g = (idx >> 10) & 63, o = idx & 1023;
    g_Sc[idx] = scale[(l << 16) + (o << 6) + g] * (1.0f / 15.0f);
}
__global__ void k_prepA(const float* __restrict__ la) {
    int idx = blockIdx.x * 256 + threadIdx.x;
    __nv_bfloat16 h, l;
    split1(la[idx], h, l);
    g_lAh[idx] = h; g_lAl[idx] = l;
}
__global__ void k_prepB(const float* __restrict__ lb) {
    int idx = blockIdx.x * 256 + threadIdx.x;
    __nv_bfloat16 h, l;
    split1(lb[idx], h, l);
    g_Bh[idx] = h; g_Bl[idx] = l;
}

// ---------------- split input x ----------------
__global__ void k_split(const float* __restrict__ x,
                        __nv_bfloat16* __restrict__ oh, __nv_bfloat16* __restrict__ ol,
                        __nv_bfloat16* __restrict__ rh, __nv_bfloat16* __restrict__ rl) {
    int i4 = blockIdx.x * blockDim.x + threadIdx.x;
    float4 v = reinterpret_cast<const float4*>(x)[i4];
    __nv_bfloat16 h0,h1,h2,h3,l0,l1,l2,l3;
    split1(v.x,h0,l0); split1(v.y,h1,l1); split1(v.z,h2,l2); split1(v.w,h3,l3);
    __nv_bfloat162 H0; H0.x=h0; H0.y=h1;
    __nv_bfloat162 H1; H1.x=h2; H1.y=h3;
    __nv_bfloat162 L0; L0.x=l0; L0.y=l1;
    __nv_bfloat162 L1; L1.x=l2; L1.y=l3;
    __nv_bfloat162* OH = reinterpret_cast<__nv_bfloat162*>(oh);
    __nv_bfloat162* OL = reinterpret_cast<__nv_bfloat162*>(ol);
    __nv_bfloat162* RH = reinterpret_cast<__nv_bfloat162*>(rh);
    __nv_bfloat162* RL = reinterpret_cast<__nv_bfloat162*>(rl);
    int b = i4 * 2;
    OH[b] = H0; OH[b+1] = H1;
    OL[b] = L0; OL[b+1] = L1;
    RH[b] = H0; RH[b+1] = H1;
    RL[b] = L0; RL[b+1] = L1;
}

// ---------------- LayerNorm ----------------
__device__ __forceinline__ float blockSum256(float v, float* red) {
#pragma unroll
    for (int o = 16; o > 0; o >>= 1) v += __shfl_xor_sync(0xffffffffu, v, o);
    int w = threadIdx.x >> 5;
    if ((threadIdx.x & 31) == 0) red[w] = v;
    __syncthreads();
    float t = 0.f;
#pragma unroll
    for (int i = 0; i < 8; i++) t += red[i];
    __syncthreads();
    return t;
}

__global__ void k_ln(const __nv_bfloat16* __restrict__ Ih, const __nv_bfloat16* __restrict__ Il,
                     const float* __restrict__ gw, const float* __restrict__ gb,
                     __nv_bfloat16* __restrict__ Oh, __nv_bfloat16* __restrict__ Ol,
                     __nv_bfloat16* __restrict__ R2h, __nv_bfloat16* __restrict__ R2l)
{
    __shared__ float red[8];
    const int row = blockIdx.x;
    const int tid = threadIdx.x;
    const size_t base = (size_t)row * DIM;
    float x[4];
#pragma unroll
    for (int j = 0; j < 4; j++) {
        int c = tid + j * 256;
        x[j] = __bfloat162float(Ih[base + c]) + __bfloat162float(Il[base + c]);
    }
    float s = x[0] + x[1] + x[2] + x[3];
    float mu = blockSum256(s, red) * (1.0f / DIM);
    float d[4], s2 = 0.f;
#pragma unroll
    for (int j = 0; j < 4; j++) { d[j] = x[j] - mu; s2 += d[j] * d[j]; }
    float var = blockSum256(s2, red) * (1.0f / DIM);
    float inv = rsqrtf(var + 1e-5f);
#pragma unroll
    for (int j = 0; j < 4; j++) {
        int c = tid + j * 256;
        float y = d[j] * inv * gw[c] + gb[c];
        __nv_bfloat16 h, l;
        split1(y, h, l);
        Oh[base + c] = h;  Ol[base + c] = l;
        R2h[base + c] = h; R2l[base + c] = l;
    }
}

// ---------------- orchestration ----------------
extern "C" void kernel_launch(void* const* d_in, const int* in_sizes, int n_in,
                              void* d_out, int out_size) {
    (void)in_sizes; (void)n_in; (void)out_size;
    const float* x     = (const float*)d_in[0];
    const float* scale = (const float*)d_in[1];
    const float* bias  = (const float*)d_in[2];
    const float* la    = (const float*)d_in[3];
    const float* lb    = (const float*)d_in[4];
    const float* lnw   = (const float*)d_in[5];
    const float* lnb   = (const float*)d_in[6];
    const int*   qw    = (const int*)d_in[7];

    __nv_bfloat16 *Wq, *lAh, *lAl, *Bh, *Bl, *Uh, *Ul;
    __nv_bfloat16 *A0h, *A0l, *A1h, *A1l, *Rh, *Rl;
    float* Sc;
    cudaGetSymbolAddress((void**)&Wq,  g_Wq);
    cudaGetSymbolAddress((void**)&Sc,  g_Sc);
    cudaGetSymbolAddress((void**)&lAh, g_lAh);
    cudaGetSymbolAddress((void**)&lAl, g_lAl);
    cudaGetSymbolAddress((void**)&Bh,  g_Bh);
    cudaGetSymbolAddress((void**)&Bl,  g_Bl);
    cudaGetSymbolAddress((void**)&Uh,  g_Uh);
    cudaGetSymbolAddress((void**)&Ul,  g_Ul);
    cudaGetSymbolAddress((void**)&A0h, g_A0h);
    cudaGetSymbolAddress((void**)&A0l, g_A0l);
    cudaGetSymbolAddress((void**)&A1h, g_A1h);
    cudaGetSymbolAddress((void**)&A1l, g_A1l);
    cudaGetSymbolAddress((void**)&Rh,  g_Rh);
    cudaGetSymbolAddress((void**)&Rl,  g_Rl);

    cudaFuncSetAttribute(k_gemm<0>, cudaFuncAttributeMaxDynamicSharedMemorySize, SM_TOTAL);
    cudaFuncSetAttribute(k_gemm<1>, cudaFuncAttributeMaxDynamicSharedMemorySize, SM_TOTAL);
    cudaFuncSetAttribute(k_gemm<2>, cudaFuncAttributeMaxDynamicSharedMemorySize, SM_TOTAL);
    cudaFuncSetAttribute(k_lora,    cudaFuncAttributeMaxDynamicSharedMemorySize, L_SMEM);

    k_split<<<BATCH * DIM / 4 / 256, 256>>>(x, A0h, A0l, Rh, Rl);
    k_prepW<<<NLAYERS * DIM * DIM / 256, 256>>>(qw);
    k_prepS<<<NLAYERS * 64 * DIM / 256, 256>>>(scale);
    k_prepA<<<NLAYERS * 32 * DIM / 256, 256>>>(la);
    k_prepB<<<NLAYERS * DIM * 32 / 256, 256>>>(lb);

    dim3 ggrid(DIM / BN, BATCH / BM);   // (8, 128)
    int li = 0;
    for (int blk = 0; blk < 6; ++blk) {
        __nv_bfloat16 *ih = A0h, *il = A0l, *oh = A1h, *ol = A1l;
        for (int j = 0; j < 3; ++j) {
            const size_t WO = (size_t)li * DIM * DIM;
            const size_t SO = (size_t)li * 64 * DIM;
            const size_t LO = (size_t)li * 32 * DIM;
            k_lora<<<BATCH / 64, 128, L_SMEM>>>(ih, il, lAh + LO, lAl + LO, Uh, Ul);
            if (j < 2) {
                k_gemm<0><<<ggrid, 256, SM_TOTAL>>>(ih, il, Wq + WO, Sc + SO, bias + li * DIM,
                                                    Uh, Ul, Bh + LO, Bl + LO,
                                                    oh, ol, nullptr, nullptr, nullptr);
            } else if (blk < 5) {
                k_gemm<1><<<ggrid, 256, SM_TOTAL>>>(ih, il, Wq + WO, Sc + SO, bias + li * DIM,
                                                    Uh, Ul, Bh + LO, Bl + LO,
                                                    oh, ol, Rh, Rl, nullptr);
            } else {
                k_gemm<2><<<ggrid, 256, SM_TOTAL>>>(ih, il, Wq + WO, Sc + SO, bias + li * DIM,
                                                    Uh, Ul, Bh + LO, Bl + LO,
                                                    nullptr, nullptr, Rh, Rl, (float*)d_out);
            }
            li++;
            __nv_bfloat16* th = ih; ih = oh; oh = th;
            __nv_bfloat16* tl = il; il = ol; ol = tl;
        }
        if (blk < 5) {
            k_ln<<<BATCH, 256>>>(ih, il, lnw + blk * DIM, lnb + blk * DIM, oh, ol, Rh, Rl);
            __nv_bfloat16* th = ih; ih = oh; oh = th;
            __nv_bfloat16* tl = il; il = ol; ol = tl;
            A0h = ih; A0l = il; A1h = oh; A1l = ol;
        }
    }
}

// round 11
// speedup vs baseline: 1.7568x; 1.7568x over previous
#include <cuda_runtime.h>
#include <cuda_bf16.h>
#include <cstdint>

#define DIM     1024
#define BATCH   16384
#define NLAYERS 18

// ---------------- GEMM tiling (R6 proven config) ----------------
#define BM 128
#define BN 128
#define BK 32                     // bf16 per K-chunk = 64B per row
#define NCHUNK (DIM / BK)         // 32

// smem stage: Ah/Al/Wh/Wl each 128 rows x 64B = 8KB -> stage 32KB, 2 stages = 64KB/CTA
#define OFF_AL 8192u
#define OFF_WH 16384u
#define OFF_WL 24576u
#define STAGE  32768u
#define SM_TOTAL (2 * 32768)

// ---------------- static device scratch ----------------
__device__ __align__(16) __nv_bfloat16 g_Wh[NLAYERS * DIM * DIM];
__device__ __align__(16) __nv_bfloat16 g_Wl[NLAYERS * DIM * DIM];
__device__ __align__(16) __nv_bfloat16 g_A0h[BATCH * DIM];
__device__ __align__(16) __nv_bfloat16 g_A0l[BATCH * DIM];
__device__ __align__(16) __nv_bfloat16 g_A1h[BATCH * DIM];
__device__ __align__(16) __nv_bfloat16 g_A1l[BATCH * DIM];
__device__ __align__(16) __nv_bfloat16 g_Rh [BATCH * DIM];
__device__ __align__(16) __nv_bfloat16 g_Rl [BATCH * DIM];

// ---------------- PTX helpers ----------------
__device__ __forceinline__ uint32_t smem_u32(const void* p) {
    uint32_t a;
    asm("{ .reg .u64 t; cvta.to.shared.u64 t, %1; cvt.u32.u64 %0, t; }" : "=r"(a) : "l"(p));
    return a;
}
#define CP_ASYNC16(dst, src) \
    asm volatile("cp.async.cg.shared.global [%0], [%1], 16;\n" :: "r"(dst), "l"(src))
#define CP_COMMIT() asm volatile("cp.async.commit_group;\n" ::: "memory")
#define CP_WAIT1()  asm volatile("cp.async.wait_group 1;\n" ::: "memory")
#define CP_WAIT0()  asm volatile("cp.async.wait_group 0;\n" ::: "memory")

#define LDSM_X4(r0, r1, r2, r3, addr) \
    asm volatile("ldmatrix.sync.aligned.m8n8.x4.shared.b16 {%0,%1,%2,%3}, [%4];\n" \
                 : "=r"(r0), "=r"(r1), "=r"(r2), "=r"(r3) : "r"(addr))

#define MMA4(d, a0, a1, a2, a3, b0, b1) \
    asm volatile("mma.sync.aligned.m16n8k16.row.col.f32.bf16.bf16.f32 " \
                 "{%0,%1,%2,%3},{%4,%5,%6,%7},{%8,%9},{%0,%1,%2,%3};\n" \
                 : "+f"((d)[0]), "+f"((d)[1]), "+f"((d)[2]), "+f"((d)[3]) \
                 : "r"(a0), "r"(a1), "r"(a2), "r"(a3), "r"(b0), "r"(b1))

// packed f32x2 helpers (proven correct/compilable in R9 run)
#define PACK2(u, lo, hi) \
    asm volatile("mov.b64 %0, {%1, %2};\n" : "=l"(u) : "f"(lo), "f"(hi))
#define UNPACK2(lo, hi, u) \
    asm volatile("mov.b64 {%0, %1}, %2;\n" : "=f"(lo), "=f"(hi) : "l"(u))
#define FMA2(a, b, c) \
    asm volatile("fma.rn.f32x2 %0, %1, %2, %0;\n" : "+l"(a) : "l"(b), "l"(c))

__device__ __forceinline__ void split1(float v, __nv_bfloat16& h, __nv_bfloat16& l) {
    h = __float2bfloat16(v);
    l = __float2bfloat16(v - __bfloat162float(h));
}

// swizzle for 64B rows: 16B-group g XOR (row & 3) — verified conflict-free (R6)
__device__ __forceinline__ uint32_t swz64(uint32_t row, uint32_t g16) {
    return row * 64u + ((g16 ^ (row & 3u)) << 4);
}

// stage loader: 32KB / 256 threads = 8 cp.async x16B per thread
__device__ __forceinline__ void load_chunk(
    uint32_t st, int c, int tid,
    const char* pAh, const char* pAl, const char* pWh, const char* pWl)
{
    const size_t koff = (size_t)c * 64u;
#pragma unroll
    for (int i = 0; i < 8; i++) {
        int idx = tid + i * 256;          // 0..2047
        int arr = idx >> 9;               // 0..3 : Ah, Al, Wh, Wl
        int r   = (idx >> 2) & 127;       // row 0..127
        int g   = idx & 3;                // 16B group 0..3
        const char* base = (arr == 0) ? pAh : (arr == 1) ? pAl : (arr == 2) ? pWh : pWl;
        const char* src = base + (size_t)r * 2048 + koff + (size_t)(g * 16);
        uint32_t dst = st + (uint32_t)arr * 8192u + swz64((uint32_t)r, (uint32_t)g);
        CP_ASYNC16(dst, src);
    }
    CP_COMMIT();
}

// ---------------- fused GEMM layer (R6 exact) ----------------
// C[BM,BN] = A[BM,K] * W[BN,K]^T, 3-term bf16 split, fp32 accum.
// MODE 0: relu(C+bias)->bf16 pair | MODE 1: C+bias+res->bf16 pair | MODE 2: C+bias+res->fp32
template<int MODE>
__global__ void __launch_bounds__(256, 2)
k_gemm(const __nv_bfloat16* __restrict__ Ah, const __nv_bfloat16* __restrict__ Al,
       const __nv_bfloat16* __restrict__ Wh, const __nv_bfloat16* __restrict__ Wl,
       const float* __restrict__ bias,
       __nv_bfloat16* __restrict__ Oh, __nv_bfloat16* __restrict__ Ol,
       const __nv_bfloat16* __restrict__ Rh, const __nv_bfloat16* __restrict__ Rl,
       float* __restrict__ Of)
{
    extern __shared__ char smem[];
    const uint32_t sb = smem_u32(smem);
    const int tid = threadIdx.x, wid = tid >> 5, lane = tid & 31;
    const int Mb = blockIdx.y * BM, Nb = blockIdx.x * BN;
    const int wm = (wid & 1) * 64;          // 2 m-warps
    const int wn = (wid >> 1) * 32;         // 4 n-warps

    const char* pAh = (const char*)(Ah + (size_t)Mb * DIM);
    const char* pAl = (const char*)(Al + (size_t)Mb * DIM);
    const char* pWh = (const char*)(Wh + (size_t)Nb * DIM);
    const char* pWl = (const char*)(Wl + (size_t)Nb * DIM);

    const int l7  = lane & 7;
    const int l15 = lane & 15;
    const int lhi = lane >> 4;              // 0/1
    const int lb8 = ((lane >> 3) & 1) << 3;

    uint32_t adA[2][4], adB[2][2];
#pragma unroll
    for (int kk = 0; kk < 2; kk++) {
#pragma unroll
        for (int mi = 0; mi < 4; mi++) {
            uint32_t r = (uint32_t)(wm + mi * 16 + l15);
            adA[kk][mi] = swz64(r, (uint32_t)(2 * kk + lhi));
        }
#pragma unroll
        for (int j = 0; j < 2; j++) {
            uint32_t r = (uint32_t)(wn + j * 16 + l7 + lb8);
            adB[kk][j] = swz64(r, (uint32_t)(2 * kk + lhi));
        }
    }

    float acc[4][4][4];
#pragma unroll
    for (int mi = 0; mi < 4; mi++)
#pragma unroll
        for (int ni = 0; ni < 4; ni++)
#pragma unroll
            for (int k = 0; k < 4; k++) acc[mi][ni][k] = 0.f;

    load_chunk(sb, 0, tid, pAh, pAl, pWh, pWl);

#pragma unroll 1
    for (int c = 0; c < NCHUNK; c++) {
        const uint32_t st = sb + (uint32_t)(c & 1) * STAGE;
        if (c + 1 < NCHUNK) {
            load_chunk(sb + (uint32_t)((c + 1) & 1) * STAGE, c + 1, tid, pAh, pAl, pWh, pWl);
            CP_WAIT1();
        } else {
            CP_WAIT0();
        }
        __syncthreads();

        const uint32_t stAh = st, stAl = st + OFF_AL, stWh = st + OFF_WH, stWl = st + OFF_WL;
#pragma unroll
        for (int kk = 0; kk < 2; kk++) {
            uint32_t aH[4][4], bH[2][4];
#pragma unroll
            for (int mi = 0; mi < 4; mi++)
                LDSM_X4(aH[mi][0], aH[mi][1], aH[mi][2], aH[mi][3], stAh + adA[kk][mi]);
#pragma unroll
            for (int j = 0; j < 2; j++)
                LDSM_X4(bH[j][0], bH[j][1], bH[j][2], bH[j][3], stWh + adB[kk][j]);
            // T1: Ah*Wh
#pragma unroll
            for (int mi = 0; mi < 4; mi++)
#pragma unroll
                for (int j = 0; j < 2; j++) {
                    MMA4(acc[mi][2 * j],     aH[mi][0], aH[mi][1], aH[mi][2], aH[mi][3], bH[j][0], bH[j][2]);
                    MMA4(acc[mi][2 * j + 1], aH[mi][0], aH[mi][1], aH[mi][2], aH[mi][3], bH[j][1], bH[j][3]);
                }
            // T3: Al*Wh (bH live)
            {
                uint32_t aL[4][4];
#pragma unroll
                for (int mi = 0; mi < 4; mi++)
                    LDSM_X4(aL[mi][0], aL[mi][1], aL[mi][2], aL[mi][3], stAl + adA[kk][mi]);
#pragma unroll
                for (int mi = 0; mi < 4; mi++)
#pragma unroll
                    for (int j = 0; j < 2; j++) {
                        MMA4(acc[mi][2 * j],     aL[mi][0], aL[mi][1], aL[mi][2], aL[mi][3], bH[j][0], bH[j][2]);
                        MMA4(acc[mi][2 * j + 1], aL[mi][0], aL[mi][1], aL[mi][2], aL[mi][3], bH[j][1], bH[j][3]);
                    }
            }
            // T2: Ah*Wl (aH live)
            {
                uint32_t bL[2][4];
#pragma unroll
                for (int j = 0; j < 2; j++)
                    LDSM_X4(bL[j][0], bL[j][1], bL[j][2], bL[j][3], stWl + adB[kk][j]);
#pragma unroll
                for (int mi = 0; mi < 4; mi++)
#pragma unroll
                    for (int j = 0; j < 2; j++) {
                        MMA4(acc[mi][2 * j],     aH[mi][0], aH[mi][1], aH[mi][2], aH[mi][3], bL[j][0], bL[j][2]);
                        MMA4(acc[mi][2 * j + 1], aH[mi][0], aH[mi][1], aH[mi][2], aH[mi][3], bL[j][1], bL[j][3]);
                    }
            }
        }
        __syncthreads();
    }

    // ---- epilogue (verified fragment layout) ----
    auto emit = [&](int r, int c, float v0, float v1) {
        size_t off = (size_t)r * DIM + c;
        if (MODE >= 1) {
            __nv_bfloat162 rh2 = *reinterpret_cast<const __nv_bfloat162*>(Rh + off);
            __nv_bfloat162 rl2 = *reinterpret_cast<const __nv_bfloat162*>(Rl + off);
            v0 += __bfloat162float(rh2.x) + __bfloat162float(rl2.x);
            v1 += __bfloat162float(rh2.y) + __bfloat162float(rl2.y);
        }
        if (MODE == 0) { v0 = fmaxf(v0, 0.f); v1 = fmaxf(v1, 0.f); }
        if (MODE == 2) {
            *reinterpret_cast<float2*>(Of + off) = make_float2(v0, v1);
        } else {
            __nv_bfloat16 h0, l0, h1, l1;
            split1(v0, h0, l0); split1(v1, h1, l1);
            __nv_bfloat162 H; H.x = h0; H.y = h1;
            __nv_bfloat162 L; L.x = l0; L.y = l1;
            *reinterpret_cast<__nv_bfloat162*>(Oh + off) = H;
            *reinterpret_cast<__nv_bfloat162*>(Ol + off) = L;
        }
    };

    const int g  = lane >> 2;
    const int tg = lane & 3;
#pragma unroll
    for (int mi = 0; mi < 4; mi++) {
#pragma unroll
        for (int ni = 0; ni < 4; ni++) {
            int r0 = Mb + wm + mi * 16 + g;
            int c0 = Nb + wn + ni * 8 + tg * 2;
            float b0 = __ldg(bias + c0), b1 = __ldg(bias + c0 + 1);
            emit(r0,     c0, acc[mi][ni][0] + b0, acc[mi][ni][1] + b1);
            emit(r0 + 8, c0, acc[mi][ni][2] + b0, acc[mi][ni][3] + b1);
        }
    }
}

// ---------------- split input x ----------------
__global__ void k_split(const float* __restrict__ x,
                        __nv_bfloat16* __restrict__ oh, __nv_bfloat16* __restrict__ ol,
                        __nv_bfloat16* __restrict__ rh, __nv_bfloat16* __restrict__ rl) {
    int i4 = blockIdx.x * blockDim.x + threadIdx.x;
    float4 v = reinterpret_cast<const float4*>(x)[i4];
    __nv_bfloat16 h0,h1,h2,h3,l0,l1,l2,l3;
    split1(v.x,h0,l0); split1(v.y,h1,l1); split1(v.z,h2,l2); split1(v.w,h3,l3);
    __nv_bfloat162 H0; H0.x=h0; H0.y=h1;
    __nv_bfloat162 H1; H1.x=h2; H1.y=h3;
    __nv_bfloat162 L0; L0.x=l0; L0.y=l1;
    __nv_bfloat162 L1; L1.x=l2; L1.y=l3;
    __nv_bfloat162* OH = reinterpret_cast<__nv_bfloat162*>(oh);
    __nv_bfloat162* OL = reinterpret_cast<__nv_bfloat162*>(ol);
    __nv_bfloat162* RH = reinterpret_cast<__nv_bfloat162*>(rh);
    __nv_bfloat162* RL = reinterpret_cast<__nv_bfloat162*>(rl);
    int b = i4 * 2;
    OH[b] = H0; OH[b+1] = H1;
    OL[b] = L0; OL[b+1] = L1;
    RH[b] = H0; RH[b+1] = H1;
    RL[b] = L0; RL[b+1] = L1;
}

// ---------------- dequant + fold LoRA (f32x2 version: 2 outputs/thread) ----------------
// w[i] = (q/15*2-1)*s  +  sum_r lb[o][r] * la[r][i]   (dequant formula identical to R6)
__global__ void __launch_bounds__(256)
k_prep(const int* __restrict__ qw, const float* __restrict__ scale,
       const float* __restrict__ la, const float* __restrict__ lb) {
    int idx2 = blockIdx.x * 256 + threadIdx.x;        // < 18*1024*512
    int l    = idx2 >> 19;
    int rem  = idx2 & 0x7FFFF;
    int o    = rem >> 9;
    int i    = (rem & 511) * 2;                       // even i -> pair (i, i+1), same 16-group

    size_t base = ((size_t)l << 20) + ((size_t)o << 10) + (size_t)i;
    int2 q2 = *reinterpret_cast<const int2*>(qw + base);
    float s = scale[(l << 16) + (o << 6) + (i >> 4)];
    float w0 = ((float)q2.x / 15.0f * 2.0f - 1.0f) * s;
    float w1 = ((float)q2.y / 15.0f * 2.0f - 1.0f) * s;

    // hoist lb[o][0..31] via 8 x float4
    const float4* lb4 = reinterpret_cast<const float4*>(lb + l * (DIM * 32) + o * 32);
    float lbv[32];
#pragma unroll
    for (int q = 0; q < 8; q++) {
        float4 v = lb4[q];
        lbv[q * 4]     = v.x; lbv[q * 4 + 1] = v.y;
        lbv[q * 4 + 2] = v.z; lbv[q * 4 + 3] = v.w;
    }

    const float* lar = la + l * (32 * DIM) + i;       // + r*DIM over r, float2-aligned
    unsigned long long accp;
    PACK2(accp, w0, w1);
#pragma unroll
    for (int r = 0; r < 32; r++) {
        float2 a2 = *reinterpret_cast<const float2*>(lar + (size_t)r * DIM);
        unsigned long long ap, bp;
        PACK2(ap, a2.x, a2.y);
        PACK2(bp, lbv[r], lbv[r]);
        FMA2(accp, bp, ap);
    }
    float r0, r1;
    UNPACK2(r0, r1, accp);

    __nv_bfloat16 h0, l0, h1, l1;
    split1(r0, h0, l0);
    split1(r1, h1, l1);
    __nv_bfloat162 H; H.x = h0; H.y = h1;
    __nv_bfloat162 L; L.x = l0; L.y = l1;
    *reinterpret_cast<__nv_bfloat162*>(g_Wh + base) = H;
    *reinterpret_cast<__nv_bfloat162*>(g_Wl + base) = L;
}

// ---------------- LayerNorm ----------------
__device__ __forceinline__ float blockSum256(float v, float* red) {
#pragma unroll
    for (int o = 16; o > 0; o >>= 1) v += __shfl_xor_sync(0xffffffffu, v, o);
    int w = threadIdx.x >> 5;
    if ((threadIdx.x & 31) == 0) red[w] = v;
    __syncthreads();
    float t = 0.f;
#pragma unroll
    for (int i = 0; i < 8; i++) t += red[i];
    __syncthreads();
    return t;
}

__global__ void k_ln(const __nv_bfloat16* __restrict__ Ih, const __nv_bfloat16* __restrict__ Il,
                     const float* __restrict__ gw, const float* __restrict__ gb,
                     __nv_bfloat16* __restrict__ Oh, __nv_bfloat16* __restrict__ Ol,
                     __nv_bfloat16* __restrict__ R2h, __nv_bfloat16* __restrict__ R2l)
{
    __shared__ float red[8];
    const int row = blockIdx.x;
    const int tid = threadIdx.x;
    const size_t base = (size_t)row * DIM;
    float x[4];
#pragma unroll
    for (int j = 0; j < 4; j++) {
        int c = tid + j * 256;
        x[j] = __bfloat162float(Ih[base + c]) + __bfloat162float(Il[base + c]);
    }
    float s = x[0] + x[1] + x[2] + x[3];
    float mu = blockSum256(s, red) * (1.0f / DIM);
    float d[4], s2 = 0.f;
#pragma unroll
    for (int j = 0; j < 4; j++) { d[j] = x[j] - mu; s2 += d[j] * d[j]; }
    float var = blockSum256(s2, red) * (1.0f / DIM);
    float inv = rsqrtf(var + 1e-5f);
#pragma unroll
    for (int j = 0; j < 4; j++) {
        int c = tid + j * 256;
        float y = d[j] * inv * gw[c] + gb[c];
        __nv_bfloat16 h, l;
        split1(y, h, l);
        Oh[base + c] = h;  Ol[base + c] = l;
        R2h[base + c] = h; R2l[base + c] = l;
    }
}

// ---------------- orchestration (R6 exact) ----------------
extern "C" void kernel_launch(void* const* d_in, const int* in_sizes, int n_in,
                              void* d_out, int out_size) {
    (void)in_sizes; (void)n_in; (void)out_size;
    const float* x     = (const float*)d_in[0];
    const float* scale = (const float*)d_in[1];
    const float* bias  = (const float*)d_in[2];
    const float* la    = (const float*)d_in[3];
    const float* lb    = (const float*)d_in[4];
    const float* lnw   = (const float*)d_in[5];
    const float* lnb   = (const float*)d_in[6];
    const int*   qw    = (const int*)d_in[7];

    __nv_bfloat16 *Wh, *Wl, *A0h, *A0l, *A1h, *A1l, *Rh, *Rl;
    cudaGetSymbolAddress((void**)&Wh,  g_Wh);
    cudaGetSymbolAddress((void**)&Wl,  g_Wl);
    cudaGetSymbolAddress((void**)&A0h, g_A0h);
    cudaGetSymbolAddress((void**)&A0l, g_A0l);
    cudaGetSymbolAddress((void**)&A1h, g_A1h);
    cudaGetSymbolAddress((void**)&A1l, g_A1l);
    cudaGetSymbolAddress((void**)&Rh,  g_Rh);
    cudaGetSymbolAddress((void**)&Rl,  g_Rl);

    cudaFuncSetAttribute(k_gemm<0>, cudaFuncAttributeMaxDynamicSharedMemorySize, SM_TOTAL);
    cudaFuncSetAttribute(k_gemm<1>, cudaFuncAttributeMaxDynamicSharedMemorySize, SM_TOTAL);
    cudaFuncSetAttribute(k_gemm<2>, cudaFuncAttributeMaxDynamicSharedMemorySize, SM_TOTAL);

    k_split<<<BATCH * DIM / 4 / 256, 256>>>(x, A0h, A0l, Rh, Rl);
    k_prep <<<NLAYERS * DIM * DIM / 2 / 256, 256>>>(qw, scale, la, lb);

    dim3 ggrid(DIM / BN, BATCH / BM);   // (8, 128)
    int li = 0;
    for (int blk = 0; blk < 6; ++blk) {
        const int W0 = li * DIM * DIM;
        k_gemm<0><<<ggrid, 256, SM_TOTAL>>>(A0h, A0l, Wh + W0, Wl + W0, bias + li * DIM,
                                            A1h, A1l, nullptr, nullptr, nullptr);
        li++;
        const int W1 = li * DIM * DIM;
        k_gemm<0><<<ggrid, 256, SM_TOTAL>>>(A1h, A1l, Wh + W1, Wl + W1, bias + li * DIM,
                                            A0h, A0l, nullptr, nullptr, nullptr);
        li++;
        const int W2 = li * DIM * DIM;
        if (blk < 5) {
            k_gemm<1><<<ggrid, 256, SM_TOTAL>>>(A0h, A0l, Wh + W2, Wl + W2, bias + li * DIM,
                                                A1h, A1l, Rh, Rl, nullptr);
            li++;
            k_ln<<<BATCH, 256>>>(A1h, A1l, lnw + blk * DIM, lnb + blk * DIM,
                                 A0h, A0l, Rh, Rl);
        } else {
            k_gemm<2><<<ggrid, 256, SM_TOTAL>>>(A0h, A0l, Wh + W2, Wl + W2, bias + li * DIM,
                                                nullptr, nullptr, Rh, Rl, (float*)d_out);
            li++;
        }
    }
}